// round 7
// baseline (speedup 1.0000x reference)
#include <cuda_runtime.h>
#include <math.h>
#include <stdint.h>

#define N_PTS 2000000
#define N_CLU 65536
#define N_THREADS_PT (N_PTS / 4)   // 500000 threads, 4 consecutive sorted pts each

__device__ float g_agg[N_CLU * 64];
__device__ float g_mid[N_CLU * 128];       // blocked: [c/32][k][c%32]
__device__ int   g_cnt[N_CLU];
__device__ int   g_cur[N_CLU];
__device__ int   g_bsum[64];
__device__ int   g_slbl[N_PTS];
__device__ __align__(16) float g_sdata[(size_t)N_PTS * 12];  // sorted [pf0..7, d0..2, pad]

// ---------------------------------------------------------------------------
__device__ __forceinline__ uint64_t pack2(float lo, float hi) {
    uint64_t r; asm("mov.b64 %0,{%1,%2};" : "=l"(r) : "f"(lo), "f"(hi)); return r;
}
__device__ __forceinline__ float2 unpack2(uint64_t v) {
    float2 r; asm("mov.b64 {%0,%1},%2;" : "=f"(r.x), "=f"(r.y) : "l"(v)); return r;
}
__device__ __forceinline__ uint64_t fma2(uint64_t a, uint64_t b, uint64_t c) {
    uint64_t d; asm("fma.rn.f32x2 %0,%1,%2,%3;" : "=l"(d) : "l"(a), "l"(b), "l"(c)); return d;
}
__device__ __forceinline__ uint64_t mul2(uint64_t a, uint64_t b) {
    uint64_t d; asm("mul.rn.f32x2 %0,%1,%2;" : "=l"(d) : "l"(a), "l"(b)); return d;
}
__device__ __forceinline__ uint64_t relu2(uint64_t v) {
    float2 f = unpack2(v);
    return pack2(fmaxf(f.x, 0.0f), fmaxf(f.y, 0.0f));
}
__device__ __forceinline__ void red4(float* p, float a, float b, float c, float d) {
    asm volatile("red.global.add.v4.f32 [%0], {%1,%2,%3,%4};"
                 :: "l"(p), "f"(a), "f"(b), "f"(c), "f"(d) : "memory");
}

// ---------------------------------------------------------------------------
// zero + counting sort
// ---------------------------------------------------------------------------
__global__ void k_zero_agg() {
    int i = blockIdx.x * 256 + threadIdx.x;
    ((float4*)g_agg)[i] = make_float4(0.f, 0.f, 0.f, 0.f);
}
__global__ void k_zero_cnt() {
    int i = blockIdx.x * 256 + threadIdx.x;
    ((int4*)g_cnt)[i] = make_int4(0, 0, 0, 0);
}
__global__ void k_hist(const int* __restrict__ labels) {
    int i = blockIdx.x * 256 + threadIdx.x;
    if (i < N_PTS) atomicAdd(&g_cnt[labels[i]], 1);
}
__global__ __launch_bounds__(256) void k_scan1() {
    __shared__ int sp[256];
    int t = threadIdx.x, b = blockIdx.x;
    int base = b * 1024 + t * 4;
    int4 c = *(const int4*)(g_cnt + base);
    int sum = c.x + c.y + c.z + c.w;
    sp[t] = sum;
    __syncthreads();
    for (int o = 1; o < 256; o <<= 1) {
        int v = (t >= o) ? sp[t - o] : 0;
        __syncthreads();
        sp[t] += v;
        __syncthreads();
    }
    int excl = sp[t] - sum;
    int4 ov;
    ov.x = excl; ov.y = excl + c.x; ov.z = ov.y + c.y; ov.w = ov.z + c.z;
    *(int4*)(g_cur + base) = ov;
    if (t == 255) g_bsum[b] = sp[255];
}
__global__ void k_scan2() {
    __shared__ int sp[64];
    int t = threadIdx.x;
    int v = g_bsum[t];
    sp[t] = v;
    __syncthreads();
    for (int o = 1; o < 64; o <<= 1) {
        int u = (t >= o) ? sp[t - o] : 0;
        __syncthreads();
        sp[t] += u;
        __syncthreads();
    }
    g_bsum[t] = sp[t] - v;
}
__global__ __launch_bounds__(256) void k_scan3() {
    int t = threadIdx.x, b = blockIdx.x;
    int off = g_bsum[b];
    int base = b * 1024 + t * 4;
    int4 v = *(const int4*)(g_cur + base);
    v.x += off; v.y += off; v.z += off; v.w += off;
    *(int4*)(g_cur + base) = v;
}

// scatter + materialize edge inputs: coalesced reads, random 48B writes
__global__ void k_scatter(const float* __restrict__ pf,
                          const float* __restrict__ pts,
                          const float* __restrict__ cc,
                          const int* __restrict__ labels) {
    int i = blockIdx.x * 256 + threadIdx.x;
    if (i >= N_PTS) return;
    int l = labels[i];
    int pos = atomicAdd(&g_cur[l], 1);
    g_slbl[pos] = l;
    float4 v0 = ((const float4*)pf)[(size_t)i * 2];
    float4 v1 = ((const float4*)pf)[(size_t)i * 2 + 1];
    float d0 = cc[(size_t)l * 3 + 0] - pts[(size_t)i * 3 + 0];
    float d1 = cc[(size_t)l * 3 + 1] - pts[(size_t)i * 3 + 1];
    float d2 = cc[(size_t)l * 3 + 2] - pts[(size_t)i * 3 + 2];
    float4* dst = (float4*)(g_sdata + (size_t)pos * 12);
    dst[0] = v0;
    dst[1] = v1;
    dst[2] = make_float4(d0, d1, d2, 0.0f);
}

// ---------------------------------------------------------------------------
// Kernel 1: per-point MLPs over 4 CONSECUTIVE SORTED points per thread.
// Inputs pre-gathered in g_sdata (coalesced). Merged red4 scatter.
// ---------------------------------------------------------------------------
__global__ __launch_bounds__(128) void k_point(
    const float* __restrict__ we0, const float* __restrict__ be0,
    const float* __restrict__ we1, const float* __restrict__ be1,
    const float* __restrict__ we2, const float* __restrict__ be2,
    const float* __restrict__ we3, const float* __restrict__ be3,
    const float* __restrict__ wa0, const float* __restrict__ ba0,
    const float* __restrict__ wa1, const float* __restrict__ ba1)
{
    __shared__ __align__(16) uint64_t s[3730];
    uint64_t* sWE0 = s + 0;     // 88
    uint64_t* sBE0 = s + 88;    // 8
    uint64_t* sWE1 = s + 96;    // 128
    uint64_t* sBE1 = s + 224;   // 16
    uint64_t* sWE2 = s + 240;   // 512
    uint64_t* sBE2 = s + 752;   // 32
    uint64_t* sWE3 = s + 784;   // 2048
    uint64_t* sBE3 = s + 2832;  // 64
    uint64_t* sWA0 = s + 2896;  // 704
    uint64_t* sBA0 = s + 3600;  // 64
    uint64_t* sWA1 = s + 3664;  // 64
    uint64_t* sBA1 = s + 3728;  // 1

    const int t = threadIdx.x;
    {
        #define DUP(dst, src, n) for (int i = t; i < (n); i += 128) { float v = (src)[i]; (dst)[i] = pack2(v, v); }
        DUP(sWE0, we0, 88)   DUP(sBE0, be0, 8)
        DUP(sWE1, we1, 128)  DUP(sBE1, be1, 16)
        DUP(sWE2, we2, 512)  DUP(sBE2, be2, 32)
        DUP(sWE3, we3, 2048) DUP(sBE3, be3, 64)
        DUP(sWA0, wa0, 704)  DUP(sBA0, ba0, 64)
        DUP(sWA1, wa1, 64)   DUP(sBA1, ba1, 1)
        #undef DUP
    }
    __syncthreads();

    const int gid = blockIdx.x * 128 + t;
    if (gid >= N_THREADS_PT) return;
    const int pos0 = gid * 4;

    const int4 slbl = *(const int4*)(g_slbl + pos0);
    const int lbl[4] = {slbl.x, slbl.y, slbl.z, slbl.w};

    // pair q packs points (2q, 2q+1); coalesced 48B-per-point loads
    uint64_t x2[2][11];
#pragma unroll
    for (int q = 0; q < 2; q++) {
        const float4* pa = (const float4*)(g_sdata + (size_t)(pos0 + 2 * q) * 12);
        const float4* pb = (const float4*)(g_sdata + (size_t)(pos0 + 2 * q + 1) * 12);
        float4 a0 = pa[0], a1 = pa[1], a2v = pa[2];
        float4 b0 = pb[0], b1 = pb[1], b2v = pb[2];
        x2[q][0] = pack2(a0.x, b0.x); x2[q][1] = pack2(a0.y, b0.y);
        x2[q][2] = pack2(a0.z, b0.z); x2[q][3] = pack2(a0.w, b0.w);
        x2[q][4] = pack2(a1.x, b1.x); x2[q][5] = pack2(a1.y, b1.y);
        x2[q][6] = pack2(a1.z, b1.z); x2[q][7] = pack2(a1.w, b1.w);
        x2[q][8] = pack2(a2v.x, b2v.x);
        x2[q][9] = pack2(a2v.y, b2v.y);
        x2[q][10] = pack2(a2v.z, b2v.z);
    }

    // ----- attention: j-pairs -----
    uint64_t aa0 = sBA1[0], aa1 = aa0;
#pragma unroll 2
    for (int j = 0; j < 64; j += 2) {
        ulonglong2 b = *(const ulonglong2*)&sBA0[j];
        uint64_t c00 = b.x, c01 = b.y, c10 = b.x, c11 = b.y;
#pragma unroll
        for (int k = 0; k < 11; k++) {
            ulonglong2 w = *(const ulonglong2*)&sWA0[k * 64 + j];
            c00 = fma2(x2[0][k], w.x, c00); c01 = fma2(x2[0][k], w.y, c01);
            c10 = fma2(x2[1][k], w.x, c10); c11 = fma2(x2[1][k], w.y, c11);
        }
        ulonglong2 w1 = *(const ulonglong2*)&sWA1[j];
        aa0 = fma2(relu2(c00), w1.x, aa0); aa0 = fma2(relu2(c01), w1.y, aa0);
        aa1 = fma2(relu2(c10), w1.x, aa1); aa1 = fma2(relu2(c11), w1.y, aa1);
    }
    uint64_t a2[2];
    {
        float2 v0 = unpack2(aa0), v1 = unpack2(aa1);
        a2[0] = pack2(1.0f / (1.0f + __expf(-v0.x)), 1.0f / (1.0f + __expf(-v0.y)));
        a2[1] = pack2(1.0f / (1.0f + __expf(-v1.x)), 1.0f / (1.0f + __expf(-v1.y)));
    }

    // ----- edge L0: 11 -> 8 -----
    uint64_t h0[2][8];
#pragma unroll
    for (int j = 0; j < 8; j += 2) {
        ulonglong2 b = *(const ulonglong2*)&sBE0[j];
        uint64_t c00 = b.x, c01 = b.y, c10 = b.x, c11 = b.y;
#pragma unroll
        for (int k = 0; k < 11; k++) {
            ulonglong2 w = *(const ulonglong2*)&sWE0[k * 8 + j];
            c00 = fma2(x2[0][k], w.x, c00); c01 = fma2(x2[0][k], w.y, c01);
            c10 = fma2(x2[1][k], w.x, c10); c11 = fma2(x2[1][k], w.y, c11);
        }
        h0[0][j] = relu2(c00); h0[0][j + 1] = relu2(c01);
        h0[1][j] = relu2(c10); h0[1][j + 1] = relu2(c11);
    }

    // ----- edge L1: 8 -> 16 -----
    uint64_t h1[2][16];
#pragma unroll
    for (int j = 0; j < 16; j += 2) {
        ulonglong2 b = *(const ulonglong2*)&sBE1[j];
        uint64_t c00 = b.x, c01 = b.y, c10 = b.x, c11 = b.y;
#pragma unroll
        for (int k = 0; k < 8; k++) {
            ulonglong2 w = *(const ulonglong2*)&sWE1[k * 16 + j];
            c00 = fma2(h0[0][k], w.x, c00); c01 = fma2(h0[0][k], w.y, c01);
            c10 = fma2(h0[1][k], w.x, c10); c11 = fma2(h0[1][k], w.y, c11);
        }
        h1[0][j] = relu2(c00); h1[0][j + 1] = relu2(c01);
        h1[1][j] = relu2(c10); h1[1][j + 1] = relu2(c11);
    }

    // ----- edge L2: 16 -> 32 -----
    uint64_t h2[2][32];
#pragma unroll 2
    for (int j = 0; j < 32; j += 2) {
        ulonglong2 b = *(const ulonglong2*)&sBE2[j];
        uint64_t c00 = b.x, c01 = b.y, c10 = b.x, c11 = b.y;
#pragma unroll
        for (int k = 0; k < 16; k++) {
            ulonglong2 w = *(const ulonglong2*)&sWE2[k * 32 + j];
            c00 = fma2(h1[0][k], w.x, c00); c01 = fma2(h1[0][k], w.y, c01);
            c10 = fma2(h1[1][k], w.x, c10); c11 = fma2(h1[1][k], w.y, c11);
        }
        h2[0][j] = relu2(c00); h2[0][j + 1] = relu2(c01);
        h2[1][j] = relu2(c10); h2[1][j + 1] = relu2(c11);
    }

    // ----- edge L3: 32 -> 64, streamed; label-merged vector scatter -----
    const bool e01 = (lbl[0] == lbl[1]);
    const bool e12 = (lbl[1] == lbl[2]);
    const bool e23 = (lbl[2] == lbl[3]);

#pragma unroll 1
    for (int j4 = 0; j4 < 16; j4++) {
        float r[4][4];
#pragma unroll
        for (int jj = 0; jj < 4; jj += 2) {
            int j = j4 * 4 + jj;
            ulonglong2 b = *(const ulonglong2*)&sBE3[j];
            uint64_t c00 = b.x, c01 = b.y, c10 = b.x, c11 = b.y;
#pragma unroll
            for (int k = 0; k < 32; k++) {
                ulonglong2 w = *(const ulonglong2*)&sWE3[k * 64 + j];
                c00 = fma2(h2[0][k], w.x, c00); c01 = fma2(h2[0][k], w.y, c01);
                c10 = fma2(h2[1][k], w.x, c10); c11 = fma2(h2[1][k], w.y, c11);
            }
            c00 = mul2(relu2(c00), a2[0]); c01 = mul2(relu2(c01), a2[0]);
            c10 = mul2(relu2(c10), a2[1]); c11 = mul2(relu2(c11), a2[1]);
            float2 f00 = unpack2(c00), f01 = unpack2(c01);
            float2 f10 = unpack2(c10), f11 = unpack2(c11);
            r[0][jj] = f00.x; r[0][jj + 1] = f01.x;
            r[1][jj] = f00.y; r[1][jj + 1] = f01.y;
            r[2][jj] = f10.x; r[2][jj + 1] = f11.x;
            r[3][jj] = f10.y; r[3][jj + 1] = f11.y;
        }

        float s0 = r[0][0], s1 = r[0][1], s2 = r[0][2], s3 = r[0][3];
        const int off = j4 * 4;
#pragma unroll
        for (int p = 1; p < 4; p++) {
            bool eq = (p == 1) ? e01 : ((p == 2) ? e12 : e23);
            if (eq) {
                s0 += r[p][0]; s1 += r[p][1]; s2 += r[p][2]; s3 += r[p][3];
            } else {
                red4(g_agg + (size_t)lbl[p - 1] * 64 + off, s0, s1, s2, s3);
                s0 = r[p][0]; s1 = r[p][1]; s2 = r[p][2]; s3 = r[p][3];
            }
        }
        red4(g_agg + (size_t)lbl[3] * 64 + off, s0, s1, s2, s3);
    }
}

// ---------------------------------------------------------------------------
// Kernel 2: g_mid = relu(g_agg @ wo0 + bo0). 16 clusters/block.
// ---------------------------------------------------------------------------
__global__ __launch_bounds__(256) void k_mid(
    const float* __restrict__ wo0, const float* __restrict__ bo0)
{
    __shared__ float sw[64 * 128];
    __shared__ float sb[128];
    __shared__ __align__(16) float saggT[64 * 16];

    const int t  = threadIdx.x;
    const int cb = blockIdx.x * 16;

    for (int i = t; i < 8192; i += 256) sw[i] = wo0[i];
    if (t < 128) sb[t] = bo0[t];
    {
        int c  = t >> 4;
        int k4 = t & 15;
        float4 v = ((const float4*)g_agg)[(size_t)(cb + c) * 16 + k4];
        saggT[(k4 * 4 + 0) * 16 + c] = v.x;
        saggT[(k4 * 4 + 1) * 16 + c] = v.y;
        saggT[(k4 * 4 + 2) * 16 + c] = v.z;
        saggT[(k4 * 4 + 3) * 16 + c] = v.w;
    }
    __syncthreads();

    const int j    = t & 127;
    const int half = t >> 7;

    uint64_t acc[4];
    {
        float b = sb[j];
#pragma unroll
        for (int p = 0; p < 4; p++) acc[p] = pack2(b, b);
    }

#pragma unroll 4
    for (int k = 0; k < 64; k++) {
        float w = sw[k * 128 + j];
        uint64_t w2 = pack2(w, w);
        const uint64_t* row = (const uint64_t*)(saggT + k * 16) + half * 4;
        ulonglong2 m0 = *(const ulonglong2*)(row);
        ulonglong2 m1 = *(const ulonglong2*)(row + 2);
        acc[0] = fma2(m0.x, w2, acc[0]);
        acc[1] = fma2(m0.y, w2, acc[1]);
        acc[2] = fma2(m1.x, w2, acc[2]);
        acc[3] = fma2(m1.y, w2, acc[3]);
    }

    const int group = blockIdx.x >> 1;
    const int lane0 = (blockIdx.x & 1) * 16 + half * 8;
    float* dst = g_mid + (size_t)group * 4096 + (size_t)j * 32 + lane0;
#pragma unroll
    for (int p = 0; p < 4; p++) {
        float2 f = unpack2(acc[p]);
        f.x = fmaxf(f.x, 0.0f); f.y = fmaxf(f.y, 0.0f);
        ((float2*)dst)[p] = f;
    }
}

// ---------------------------------------------------------------------------
// Kernel 3: out = relu(g_mid @ wo1 + bo1). 32 clusters/block, 128 threads.
// ---------------------------------------------------------------------------
__global__ __launch_bounds__(128) void k_out(
    const float* __restrict__ wo1, const float* __restrict__ bo1,
    float* __restrict__ out)
{
    __shared__ __align__(16) uint64_t smid[128 * 16];

    const int t    = threadIdx.x;
    const int cg   = t & 63;
    const int half = t >> 6;
    const int grp  = blockIdx.x;

    const uint64_t* gm = (const uint64_t*)(g_mid + (size_t)grp * 4096);
    for (int i = t; i < 2048; i += 128) smid[i] = gm[i];
    __syncthreads();

    uint64_t acc[4][8];
    {
        float4 b = ((const float4*)bo1)[cg];
#pragma unroll
        for (int p = 0; p < 8; p++) {
            acc[0][p] = pack2(b.x, b.x); acc[1][p] = pack2(b.y, b.y);
            acc[2][p] = pack2(b.z, b.z); acc[3][p] = pack2(b.w, b.w);
        }
    }

    const float4* w4p = (const float4*)wo1;
#pragma unroll 4
    for (int k = 0; k < 128; k++) {
        float4 w = w4p[k * 64 + cg];
        uint64_t wd0 = pack2(w.x, w.x), wd1 = pack2(w.y, w.y);
        uint64_t wd2 = pack2(w.z, w.z), wd3 = pack2(w.w, w.w);
        const uint64_t* mrow = smid + k * 16 + half * 8;
        ulonglong2 m0 = *(const ulonglong2*)(mrow);
        ulonglong2 m1 = *(const ulonglong2*)(mrow + 2);
        ulonglong2 m2 = *(const ulonglong2*)(mrow + 4);
        ulonglong2 m3 = *(const ulonglong2*)(mrow + 6);
        uint64_t m[8] = {m0.x, m0.y, m1.x, m1.y, m2.x, m2.y, m3.x, m3.y};
#pragma unroll
        for (int p = 0; p < 8; p++) {
            acc[0][p] = fma2(m[p], wd0, acc[0][p]);
            acc[1][p] = fma2(m[p], wd1, acc[1][p]);
            acc[2][p] = fma2(m[p], wd2, acc[2][p]);
            acc[3][p] = fma2(m[p], wd3, acc[3][p]);
        }
    }

#pragma unroll
    for (int p = 0; p < 8; p++) {
        int pp = half * 8 + p;
        int c0 = grp * 32 + 2 * pp;
        float2 f0 = unpack2(acc[0][p]), f1 = unpack2(acc[1][p]);
        float2 f2 = unpack2(acc[2][p]), f3 = unpack2(acc[3][p]);
        float4 o0 = make_float4(fmaxf(f0.x, 0.f), fmaxf(f1.x, 0.f),
                                fmaxf(f2.x, 0.f), fmaxf(f3.x, 0.f));
        float4 o1 = make_float4(fmaxf(f0.y, 0.f), fmaxf(f1.y, 0.f),
                                fmaxf(f2.y, 0.f), fmaxf(f3.y, 0.f));
        *(float4*)(out + (size_t)c0 * 256 + 4 * cg)       = o0;
        *(float4*)(out + (size_t)(c0 + 1) * 256 + 4 * cg) = o1;
    }
}

// ---------------------------------------------------------------------------
extern "C" void kernel_launch(void* const* d_in, const int* in_sizes, int n_in,
                              void* d_out, int out_size)
{
    const float* pf     = (const float*)d_in[0];
    const int*   labels = (const int*)  d_in[1];
    const float* cc     = (const float*)d_in[2];
    const float* pts    = (const float*)d_in[3];
    const float* we0    = (const float*)d_in[4];
    const float* be0    = (const float*)d_in[5];
    const float* we1    = (const float*)d_in[6];
    const float* be1    = (const float*)d_in[7];
    const float* we2    = (const float*)d_in[8];
    const float* be2    = (const float*)d_in[9];
    const float* we3    = (const float*)d_in[10];
    const float* be3    = (const float*)d_in[11];
    const float* wa0    = (const float*)d_in[12];
    const float* ba0    = (const float*)d_in[13];
    const float* wa1    = (const float*)d_in[14];
    const float* ba1    = (const float*)d_in[15];
    const float* wo0    = (const float*)d_in[16];
    const float* bo0    = (const float*)d_in[17];
    const float* wo1    = (const float*)d_in[18];
    const float* bo1    = (const float*)d_in[19];
    float* out = (float*)d_out;

    k_zero_agg<<<N_CLU * 64 / 4 / 256, 256>>>();
    k_zero_cnt<<<N_CLU / 4 / 256, 256>>>();
    k_hist<<<(N_PTS + 255) / 256, 256>>>(labels);
    k_scan1<<<64, 256>>>();
    k_scan2<<<1, 64>>>();
    k_scan3<<<64, 256>>>();
    k_scatter<<<(N_PTS + 255) / 256, 256>>>(pf, pts, cc, labels);
    k_point<<<(N_THREADS_PT + 127) / 128, 128>>>(we0, be0, we1, be1, we2, be2, we3, be3,
                                                 wa0, ba0, wa1, ba1);
    k_mid<<<N_CLU / 16, 256>>>(wo0, bo0);
    k_out<<<N_CLU / 32, 128>>>(wo1, bo1, out);
}

// round 8
// speedup vs baseline: 1.5025x; 1.5025x over previous
#include <cuda_runtime.h>
#include <math.h>
#include <stdint.h>

#define N_PTS 2000000
#define N_CLU 65536
#define PTS_PER_TH 16
#define N_TH_PT (N_PTS / PTS_PER_TH)     // 125000 threads

__device__ float g_agg[N_CLU * 64];
__device__ float g_mid[N_CLU * 128];     // blocked: [c/32][k][c%32]
__device__ int   g_cnt[N_CLU];
__device__ int   g_cur[N_CLU];
__device__ int   g_bsum[64];
__device__ int   g_perm[N_PTS];
__device__ int   g_slbl[N_PTS];
__device__ __align__(16) float4 g_p0[N_PTS];   // sorted pf[0:4]
__device__ __align__(16) float4 g_p1[N_PTS];   // sorted pf[4:8]
__device__ __align__(16) float4 g_p2[N_PTS];   // sorted (cc-pts, pad)

// ---------------------------------------------------------------------------
__device__ __forceinline__ uint64_t pack2(float lo, float hi) {
    uint64_t r; asm("mov.b64 %0,{%1,%2};" : "=l"(r) : "f"(lo), "f"(hi)); return r;
}
__device__ __forceinline__ float2 unpack2(uint64_t v) {
    float2 r; asm("mov.b64 {%0,%1},%2;" : "=f"(r.x), "=f"(r.y) : "l"(v)); return r;
}
__device__ __forceinline__ uint64_t fma2(uint64_t a, uint64_t b, uint64_t c) {
    uint64_t d; asm("fma.rn.f32x2 %0,%1,%2,%3;" : "=l"(d) : "l"(a), "l"(b), "l"(c)); return d;
}
__device__ __forceinline__ uint64_t mul2(uint64_t a, uint64_t b) {
    uint64_t d; asm("mul.rn.f32x2 %0,%1,%2;" : "=l"(d) : "l"(a), "l"(b)); return d;
}
__device__ __forceinline__ uint64_t relu2(uint64_t v) {
    float2 f = unpack2(v);
    return pack2(fmaxf(f.x, 0.0f), fmaxf(f.y, 0.0f));
}
__device__ __forceinline__ void red4(float* p, float a, float b, float c, float d) {
    asm volatile("red.global.add.v4.f32 [%0], {%1,%2,%3,%4};"
                 :: "l"(p), "f"(a), "f"(b), "f"(c), "f"(d) : "memory");
}

// ---------------------------------------------------------------------------
// zero + counting sort (indices only) + gather
// ---------------------------------------------------------------------------
__global__ void k_zero_agg() {
    int i = blockIdx.x * 256 + threadIdx.x;
    ((float4*)g_agg)[i] = make_float4(0.f, 0.f, 0.f, 0.f);
}
__global__ void k_zero_cnt() {
    int i = blockIdx.x * 256 + threadIdx.x;
    ((int4*)g_cnt)[i] = make_int4(0, 0, 0, 0);
}
__global__ void k_hist(const int* __restrict__ labels) {
    int i = blockIdx.x * 256 + threadIdx.x;
    if (i < N_PTS) atomicAdd(&g_cnt[labels[i]], 1);
}
__global__ __launch_bounds__(256) void k_scan1() {
    __shared__ int sp[256];
    int t = threadIdx.x, b = blockIdx.x;
    int base = b * 1024 + t * 4;
    int4 c = *(const int4*)(g_cnt + base);
    int sum = c.x + c.y + c.z + c.w;
    sp[t] = sum;
    __syncthreads();
    for (int o = 1; o < 256; o <<= 1) {
        int v = (t >= o) ? sp[t - o] : 0;
        __syncthreads();
        sp[t] += v;
        __syncthreads();
    }
    int excl = sp[t] - sum;
    int4 ov;
    ov.x = excl; ov.y = excl + c.x; ov.z = ov.y + c.y; ov.w = ov.z + c.z;
    *(int4*)(g_cur + base) = ov;
    if (t == 255) g_bsum[b] = sp[255];
}
__global__ void k_scan2() {
    __shared__ int sp[64];
    int t = threadIdx.x;
    int v = g_bsum[t];
    sp[t] = v;
    __syncthreads();
    for (int o = 1; o < 64; o <<= 1) {
        int u = (t >= o) ? sp[t - o] : 0;
        __syncthreads();
        sp[t] += u;
        __syncthreads();
    }
    g_bsum[t] = sp[t] - v;
}
__global__ __launch_bounds__(256) void k_scan3() {
    int t = threadIdx.x, b = blockIdx.x;
    int off = g_bsum[b];
    int base = b * 1024 + t * 4;
    int4 v = *(const int4*)(g_cur + base);
    v.x += off; v.y += off; v.z += off; v.w += off;
    *(int4*)(g_cur + base) = v;
}
// scatter indices only (4B random stores)
__global__ void k_scatter(const int* __restrict__ labels) {
    int i = blockIdx.x * 256 + threadIdx.x;
    if (i >= N_PTS) return;
    int l = labels[i];
    int pos = atomicAdd(&g_cur[l], 1);
    g_perm[pos] = i;
    g_slbl[pos] = l;
}
// gather: random reads, coalesced plane writes
__global__ void k_gather(const float* __restrict__ pf,
                         const float* __restrict__ pts,
                         const float* __restrict__ cc) {
    int pos = blockIdx.x * 256 + threadIdx.x;
    if (pos >= N_PTS) return;
    int i = g_perm[pos];
    int l = g_slbl[pos];
    g_p0[pos] = ((const float4*)pf)[(size_t)i * 2];
    g_p1[pos] = ((const float4*)pf)[(size_t)i * 2 + 1];
    float d0 = cc[(size_t)l * 3 + 0] - pts[(size_t)i * 3 + 0];
    float d1 = cc[(size_t)l * 3 + 1] - pts[(size_t)i * 3 + 1];
    float d2 = cc[(size_t)l * 3 + 2] - pts[(size_t)i * 3 + 2];
    g_p2[pos] = make_float4(d0, d1, d2, 0.0f);
}

// ---------------------------------------------------------------------------
// k_point: 16 consecutive sorted points per thread, 4 per step (2 f32x2
// pairs, R4 body). Per-thread SMEM slot accumulates current cluster;
// red4 only at cluster boundaries.
// ---------------------------------------------------------------------------
#define SLOT_STRIDE 68   // floats; 68 % 32 == 4 -> conflict-free LDS.128

__device__ __forceinline__ void flush_slot(float* slot, int c) {
    float* dst = g_agg + (size_t)c * 64;
#pragma unroll
    for (int j4 = 0; j4 < 16; j4++) {
        float4 v = *(float4*)(slot + j4 * 4);
        red4(dst + j4 * 4, v.x, v.y, v.z, v.w);
        *(float4*)(slot + j4 * 4) = make_float4(0.f, 0.f, 0.f, 0.f);
    }
}

__global__ __launch_bounds__(128) void k_point(
    const float* __restrict__ we0, const float* __restrict__ be0,
    const float* __restrict__ we1, const float* __restrict__ be1,
    const float* __restrict__ we2, const float* __restrict__ be2,
    const float* __restrict__ we3, const float* __restrict__ be3,
    const float* __restrict__ wa0, const float* __restrict__ ba0,
    const float* __restrict__ wa1, const float* __restrict__ ba1)
{
    extern __shared__ __align__(16) uint64_t s[];
    uint64_t* sWE0 = s + 0;     // 88
    uint64_t* sBE0 = s + 88;    // 8
    uint64_t* sWE1 = s + 96;    // 128
    uint64_t* sBE1 = s + 224;   // 16
    uint64_t* sWE2 = s + 240;   // 512
    uint64_t* sBE2 = s + 752;   // 32
    uint64_t* sWE3 = s + 784;   // 2048
    uint64_t* sBE3 = s + 2832;  // 64
    uint64_t* sWA0 = s + 2896;  // 704
    uint64_t* sBA0 = s + 3600;  // 64
    uint64_t* sWA1 = s + 3664;  // 64
    uint64_t* sBA1 = s + 3728;  // 1 (pad to 3730)
    float* slots = (float*)(s + 3730);

    const int t = threadIdx.x;
    {
        #define DUP(dst, src, n) for (int i = t; i < (n); i += 128) { float v = (src)[i]; (dst)[i] = pack2(v, v); }
        DUP(sWE0, we0, 88)   DUP(sBE0, be0, 8)
        DUP(sWE1, we1, 128)  DUP(sBE1, be1, 16)
        DUP(sWE2, we2, 512)  DUP(sBE2, be2, 32)
        DUP(sWE3, we3, 2048) DUP(sBE3, be3, 64)
        DUP(sWA0, wa0, 704)  DUP(sBA0, ba0, 64)
        DUP(sWA1, wa1, 64)   DUP(sBA1, ba1, 1)
        #undef DUP
    }
    __syncthreads();

    const int gid = blockIdx.x * 128 + t;
    if (gid >= N_TH_PT) return;

    float* slot = slots + t * SLOT_STRIDE;
#pragma unroll
    for (int j4 = 0; j4 < 16; j4++)
        *(float4*)(slot + j4 * 4) = make_float4(0.f, 0.f, 0.f, 0.f);

    const int pos0 = gid * PTS_PER_TH;
    int cur = g_slbl[pos0];

#pragma unroll 1
    for (int step = 0; step < 4; step++) {
        const int pos = pos0 + step * 4;
        const int4 sl4 = *(const int4*)(g_slbl + pos);
        const int lbl[4] = {sl4.x, sl4.y, sl4.z, sl4.w};
        const bool e01 = (lbl[0] == lbl[1]);
        const bool e12 = (lbl[1] == lbl[2]);
        const bool e23 = (lbl[2] == lbl[3]);
        const bool anyb = !(e01 && e12 && e23);

        if (lbl[0] != cur) { flush_slot(slot, cur); cur = lbl[0]; }

        // build two f32x2 pairs: pair q = points (pos+2q, pos+2q+1)
        uint64_t x2[2][11];
#pragma unroll
        for (int q = 0; q < 2; q++) {
            int ia = pos + 2 * q, ib = ia + 1;
            float4 a0 = g_p0[ia], a1 = g_p1[ia], av = g_p2[ia];
            float4 b0 = g_p0[ib], b1 = g_p1[ib], bv = g_p2[ib];
            x2[q][0] = pack2(a0.x, b0.x); x2[q][1] = pack2(a0.y, b0.y);
            x2[q][2] = pack2(a0.z, b0.z); x2[q][3] = pack2(a0.w, b0.w);
            x2[q][4] = pack2(a1.x, b1.x); x2[q][5] = pack2(a1.y, b1.y);
            x2[q][6] = pack2(a1.z, b1.z); x2[q][7] = pack2(a1.w, b1.w);
            x2[q][8] = pack2(av.x, bv.x);
            x2[q][9] = pack2(av.y, bv.y);
            x2[q][10] = pack2(av.z, bv.z);
        }

        // ----- attention -----
        uint64_t aa0 = sBA1[0], aa1 = aa0;
#pragma unroll 2
        for (int j = 0; j < 64; j += 2) {
            ulonglong2 b = *(const ulonglong2*)&sBA0[j];
            uint64_t c00 = b.x, c01 = b.y, c10 = b.x, c11 = b.y;
#pragma unroll
            for (int k = 0; k < 11; k++) {
                ulonglong2 w = *(const ulonglong2*)&sWA0[k * 64 + j];
                c00 = fma2(x2[0][k], w.x, c00); c01 = fma2(x2[0][k], w.y, c01);
                c10 = fma2(x2[1][k], w.x, c10); c11 = fma2(x2[1][k], w.y, c11);
            }
            ulonglong2 w1 = *(const ulonglong2*)&sWA1[j];
            aa0 = fma2(relu2(c00), w1.x, aa0); aa0 = fma2(relu2(c01), w1.y, aa0);
            aa1 = fma2(relu2(c10), w1.x, aa1); aa1 = fma2(relu2(c11), w1.y, aa1);
        }
        uint64_t a2[2];
        {
            float2 v0 = unpack2(aa0), v1 = unpack2(aa1);
            a2[0] = pack2(1.0f / (1.0f + __expf(-v0.x)), 1.0f / (1.0f + __expf(-v0.y)));
            a2[1] = pack2(1.0f / (1.0f + __expf(-v1.x)), 1.0f / (1.0f + __expf(-v1.y)));
        }

        // ----- edge L0 -----
        uint64_t h0[2][8];
#pragma unroll
        for (int j = 0; j < 8; j += 2) {
            ulonglong2 b = *(const ulonglong2*)&sBE0[j];
            uint64_t c00 = b.x, c01 = b.y, c10 = b.x, c11 = b.y;
#pragma unroll
            for (int k = 0; k < 11; k++) {
                ulonglong2 w = *(const ulonglong2*)&sWE0[k * 8 + j];
                c00 = fma2(x2[0][k], w.x, c00); c01 = fma2(x2[0][k], w.y, c01);
                c10 = fma2(x2[1][k], w.x, c10); c11 = fma2(x2[1][k], w.y, c11);
            }
            h0[0][j] = relu2(c00); h0[0][j + 1] = relu2(c01);
            h0[1][j] = relu2(c10); h0[1][j + 1] = relu2(c11);
        }

        // ----- edge L1 -----
        uint64_t h1[2][16];
#pragma unroll
        for (int j = 0; j < 16; j += 2) {
            ulonglong2 b = *(const ulonglong2*)&sBE1[j];
            uint64_t c00 = b.x, c01 = b.y, c10 = b.x, c11 = b.y;
#pragma unroll
            for (int k = 0; k < 8; k++) {
                ulonglong2 w = *(const ulonglong2*)&sWE1[k * 16 + j];
                c00 = fma2(h0[0][k], w.x, c00); c01 = fma2(h0[0][k], w.y, c01);
                c10 = fma2(h0[1][k], w.x, c10); c11 = fma2(h0[1][k], w.y, c11);
            }
            h1[0][j] = relu2(c00); h1[0][j + 1] = relu2(c01);
            h1[1][j] = relu2(c10); h1[1][j + 1] = relu2(c11);
        }

        // ----- edge L2 -----
        uint64_t h2[2][32];
#pragma unroll 2
        for (int j = 0; j < 32; j += 2) {
            ulonglong2 b = *(const ulonglong2*)&sBE2[j];
            uint64_t c00 = b.x, c01 = b.y, c10 = b.x, c11 = b.y;
#pragma unroll
            for (int k = 0; k < 16; k++) {
                ulonglong2 w = *(const ulonglong2*)&sWE2[k * 32 + j];
                c00 = fma2(h1[0][k], w.x, c00); c01 = fma2(h1[0][k], w.y, c01);
                c10 = fma2(h1[1][k], w.x, c10); c11 = fma2(h1[1][k], w.y, c11);
            }
            h2[0][j] = relu2(c00); h2[0][j + 1] = relu2(c01);
            h2[1][j] = relu2(c10); h2[1][j + 1] = relu2(c11);
        }

        // ----- edge L3 streamed; slot-accumulate with boundary red4 -----
#pragma unroll 1
        for (int j4 = 0; j4 < 16; j4++) {
            float r[4][4];
#pragma unroll
            for (int jj = 0; jj < 4; jj += 2) {
                int j = j4 * 4 + jj;
                ulonglong2 b = *(const ulonglong2*)&sBE3[j];
                uint64_t c00 = b.x, c01 = b.y, c10 = b.x, c11 = b.y;
#pragma unroll
                for (int k = 0; k < 32; k++) {
                    ulonglong2 w = *(const ulonglong2*)&sWE3[k * 64 + j];
                    c00 = fma2(h2[0][k], w.x, c00); c01 = fma2(h2[0][k], w.y, c01);
                    c10 = fma2(h2[1][k], w.x, c10); c11 = fma2(h2[1][k], w.y, c11);
                }
                c00 = mul2(relu2(c00), a2[0]); c01 = mul2(relu2(c01), a2[0]);
                c10 = mul2(relu2(c10), a2[1]); c11 = mul2(relu2(c11), a2[1]);
                float2 f00 = unpack2(c00), f01 = unpack2(c01);
                float2 f10 = unpack2(c10), f11 = unpack2(c11);
                r[0][jj] = f00.x; r[0][jj + 1] = f01.x;
                r[1][jj] = f00.y; r[1][jj + 1] = f01.y;
                r[2][jj] = f10.x; r[2][jj + 1] = f11.x;
                r[3][jj] = f10.y; r[3][jj + 1] = f11.y;
            }

            float4 sl = *(float4*)(slot + j4 * 4);
            float s0 = r[0][0], s1 = r[0][1], s2 = r[0][2], s3 = r[0][3];
            bool seg0 = true;
#pragma unroll
            for (int p = 1; p < 4; p++) {
                bool eq = (p == 1) ? e01 : ((p == 2) ? e12 : e23);
                if (eq) {
                    s0 += r[p][0]; s1 += r[p][1]; s2 += r[p][2]; s3 += r[p][3];
                } else {
                    if (seg0) { sl.x += s0; sl.y += s1; sl.z += s2; sl.w += s3; seg0 = false; }
                    else red4(g_agg + (size_t)lbl[p - 1] * 64 + j4 * 4, s0, s1, s2, s3);
                    s0 = r[p][0]; s1 = r[p][1]; s2 = r[p][2]; s3 = r[p][3];
                }
            }
            if (seg0) { sl.x += s0; sl.y += s1; sl.z += s2; sl.w += s3; }
            else red4(g_agg + (size_t)lbl[3] * 64 + j4 * 4, s0, s1, s2, s3);
            *(float4*)(slot + j4 * 4) = sl;
        }

        if (anyb) { flush_slot(slot, cur); cur = lbl[3]; }
    }

    flush_slot(slot, cur);
}

// ---------------------------------------------------------------------------
// Kernel 2: g_mid = relu(g_agg @ wo0 + bo0). 16 clusters/block.
// ---------------------------------------------------------------------------
__global__ __launch_bounds__(256) void k_mid(
    const float* __restrict__ wo0, const float* __restrict__ bo0)
{
    __shared__ float sw[64 * 128];
    __shared__ float sb[128];
    __shared__ __align__(16) float saggT[64 * 16];

    const int t  = threadIdx.x;
    const int cb = blockIdx.x * 16;

    for (int i = t; i < 8192; i += 256) sw[i] = wo0[i];
    if (t < 128) sb[t] = bo0[t];
    {
        int c  = t >> 4;
        int k4 = t & 15;
        float4 v = ((const float4*)g_agg)[(size_t)(cb + c) * 16 + k4];
        saggT[(k4 * 4 + 0) * 16 + c] = v.x;
        saggT[(k4 * 4 + 1) * 16 + c] = v.y;
        saggT[(k4 * 4 + 2) * 16 + c] = v.z;
        saggT[(k4 * 4 + 3) * 16 + c] = v.w;
    }
    __syncthreads();

    const int j    = t & 127;
    const int half = t >> 7;

    uint64_t acc[4];
    {
        float b = sb[j];
#pragma unroll
        for (int p = 0; p < 4; p++) acc[p] = pack2(b, b);
    }

#pragma unroll 4
    for (int k = 0; k < 64; k++) {
        float w = sw[k * 128 + j];
        uint64_t w2 = pack2(w, w);
        const uint64_t* row = (const uint64_t*)(saggT + k * 16) + half * 4;
        ulonglong2 m0 = *(const ulonglong2*)(row);
        ulonglong2 m1 = *(const ulonglong2*)(row + 2);
        acc[0] = fma2(m0.x, w2, acc[0]);
        acc[1] = fma2(m0.y, w2, acc[1]);
        acc[2] = fma2(m1.x, w2, acc[2]);
        acc[3] = fma2(m1.y, w2, acc[3]);
    }

    const int group = blockIdx.x >> 1;
    const int lane0 = (blockIdx.x & 1) * 16 + half * 8;
    float* dst = g_mid + (size_t)group * 4096 + (size_t)j * 32 + lane0;
#pragma unroll
    for (int p = 0; p < 4; p++) {
        float2 f = unpack2(acc[p]);
        f.x = fmaxf(f.x, 0.0f); f.y = fmaxf(f.y, 0.0f);
        ((float2*)dst)[p] = f;
    }
}

// ---------------------------------------------------------------------------
// Kernel 3: out = relu(g_mid @ wo1 + bo1). 32 clusters/block, 128 threads.
// ---------------------------------------------------------------------------
__global__ __launch_bounds__(128) void k_out(
    const float* __restrict__ wo1, const float* __restrict__ bo1,
    float* __restrict__ out)
{
    __shared__ __align__(16) uint64_t smid[128 * 16];

    const int t    = threadIdx.x;
    const int cg   = t & 63;
    const int half = t >> 6;
    const int grp  = blockIdx.x;

    const uint64_t* gm = (const uint64_t*)(g_mid + (size_t)grp * 4096);
    for (int i = t; i < 2048; i += 128) smid[i] = gm[i];
    __syncthreads();

    uint64_t acc[4][8];
    {
        float4 b = ((const float4*)bo1)[cg];
#pragma unroll
        for (int p = 0; p < 8; p++) {
            acc[0][p] = pack2(b.x, b.x); acc[1][p] = pack2(b.y, b.y);
            acc[2][p] = pack2(b.z, b.z); acc[3][p] = pack2(b.w, b.w);
        }
    }

    const float4* w4p = (const float4*)wo1;
#pragma unroll 4
    for (int k = 0; k < 128; k++) {
        float4 w = w4p[k * 64 + cg];
        uint64_t wd0 = pack2(w.x, w.x), wd1 = pack2(w.y, w.y);
        uint64_t wd2 = pack2(w.z, w.z), wd3 = pack2(w.w, w.w);
        const uint64_t* mrow = smid + k * 16 + half * 8;
        ulonglong2 m0 = *(const ulonglong2*)(mrow);
        ulonglong2 m1 = *(const ulonglong2*)(mrow + 2);
        ulonglong2 m2 = *(const ulonglong2*)(mrow + 4);
        ulonglong2 m3 = *(const ulonglong2*)(mrow + 6);
        uint64_t m[8] = {m0.x, m0.y, m1.x, m1.y, m2.x, m2.y, m3.x, m3.y};
#pragma unroll
        for (int p = 0; p < 8; p++) {
            acc[0][p] = fma2(m[p], wd0, acc[0][p]);
            acc[1][p] = fma2(m[p], wd1, acc[1][p]);
            acc[2][p] = fma2(m[p], wd2, acc[2][p]);
            acc[3][p] = fma2(m[p], wd3, acc[3][p]);
        }
    }

#pragma unroll
    for (int p = 0; p < 8; p++) {
        int pp = half * 8 + p;
        int c0 = grp * 32 + 2 * pp;
        float2 f0 = unpack2(acc[0][p]), f1 = unpack2(acc[1][p]);
        float2 f2 = unpack2(acc[2][p]), f3 = unpack2(acc[3][p]);
        float4 o0 = make_float4(fmaxf(f0.x, 0.f), fmaxf(f1.x, 0.f),
                                fmaxf(f2.x, 0.f), fmaxf(f3.x, 0.f));
        float4 o1 = make_float4(fmaxf(f0.y, 0.f), fmaxf(f1.y, 0.f),
                                fmaxf(f2.y, 0.f), fmaxf(f3.y, 0.f));
        *(float4*)(out + (size_t)c0 * 256 + 4 * cg)       = o0;
        *(float4*)(out + (size_t)(c0 + 1) * 256 + 4 * cg) = o1;
    }
}

// ---------------------------------------------------------------------------
extern "C" void kernel_launch(void* const* d_in, const int* in_sizes, int n_in,
                              void* d_out, int out_size)
{
    const float* pf     = (const float*)d_in[0];
    const int*   labels = (const int*)  d_in[1];
    const float* cc     = (const float*)d_in[2];
    const float* pts    = (const float*)d_in[3];
    const float* we0    = (const float*)d_in[4];
    const float* be0    = (const float*)d_in[5];
    const float* we1    = (const float*)d_in[6];
    const float* be1    = (const float*)d_in[7];
    const float* we2    = (const float*)d_in[8];
    const float* be2    = (const float*)d_in[9];
    const float* we3    = (const float*)d_in[10];
    const float* be3    = (const float*)d_in[11];
    const float* wa0    = (const float*)d_in[12];
    const float* ba0    = (const float*)d_in[13];
    const float* wa1    = (const float*)d_in[14];
    const float* ba1    = (const float*)d_in[15];
    const float* wo0    = (const float*)d_in[16];
    const float* bo0    = (const float*)d_in[17];
    const float* wo1    = (const float*)d_in[18];
    const float* bo1    = (const float*)d_in[19];
    float* out = (float*)d_out;

    const int smem_pt = 3730 * 8 + 128 * SLOT_STRIDE * 4;   // 29840 + 34816 = 64656
    static int attr_set = 0;
    if (!attr_set) {
        cudaFuncSetAttribute(k_point, cudaFuncAttributeMaxDynamicSharedMemorySize, smem_pt);
        attr_set = 1;
    }

    k_zero_agg<<<N_CLU * 64 / 4 / 256, 256>>>();
    k_zero_cnt<<<N_CLU / 4 / 256, 256>>>();
    k_hist<<<(N_PTS + 255) / 256, 256>>>(labels);
    k_scan1<<<64, 256>>>();
    k_scan2<<<1, 64>>>();
    k_scan3<<<64, 256>>>();
    k_scatter<<<(N_PTS + 255) / 256, 256>>>(labels);
    k_gather<<<(N_PTS + 255) / 256, 256>>>(pf, pts, cc);
    k_point<<<(N_TH_PT + 127) / 128, 128, smem_pt>>>(we0, be0, we1, be1, we2, be2, we3, be3,
                                                     wa0, ba0, wa1, ba1);
    k_mid<<<N_CLU / 16, 256>>>(wo0, bo0);
    k_out<<<N_CLU / 32, 128>>>(wo1, bo1, out);
}

// round 9
// speedup vs baseline: 2.3820x; 1.5854x over previous
#include <cuda_runtime.h>
#include <cuda_fp16.h>
#include <math.h>
#include <stdint.h>

#define N_PTS 2000000
#define N_CLU 65536
#define N_GRPS (N_PTS / 16)        // 125000 16-point groups
#define GRP 8                      // groups per warp
#define WPB 8                      // warps per block
#define PT_BLOCKS ((N_GRPS + WPB * GRP - 1) / (WPB * GRP))

__device__ float g_agg[N_CLU * 64];
__device__ float g_mid[N_CLU * 128];     // blocked: [c/32][k][c%32]
__device__ int   g_cnt[N_CLU];
__device__ int   g_cur[N_CLU];
__device__ int   g_bsum[64];
__device__ int   g_perm[N_PTS];
__device__ int   g_slbl[N_PTS];
__device__ __align__(16) float4 g_p0[N_PTS];   // sorted pf[0:4]
__device__ __align__(16) float4 g_p1[N_PTS];   // sorted pf[4:8]
__device__ __align__(16) float4 g_p2[N_PTS];   // sorted (cc-pts, pad)

// ---------------------------------------------------------------------------
// helpers
// ---------------------------------------------------------------------------
__device__ __forceinline__ uint64_t pack2(float lo, float hi) {
    uint64_t r; asm("mov.b64 %0,{%1,%2};" : "=l"(r) : "f"(lo), "f"(hi)); return r;
}
__device__ __forceinline__ float2 unpack2(uint64_t v) {
    float2 r; asm("mov.b64 {%0,%1},%2;" : "=f"(r.x), "=f"(r.y) : "l"(v)); return r;
}
__device__ __forceinline__ uint64_t fma2(uint64_t a, uint64_t b, uint64_t c) {
    uint64_t d; asm("fma.rn.f32x2 %0,%1,%2,%3;" : "=l"(d) : "l"(a), "l"(b), "l"(c)); return d;
}
__device__ __forceinline__ void red2(float* p, float a, float b) {
    asm volatile("red.global.add.v2.f32 [%0],{%1,%2};" :: "l"(p), "f"(a), "f"(b) : "memory");
}
__device__ __forceinline__ uint32_t h2u(float lo, float hi) {
    __half2 h = __floats2half2_rn(lo, hi);
    return *reinterpret_cast<uint32_t*>(&h);
}
// D = A*B + D  (m16n8k16, f16 in, f32 acc)
__device__ __forceinline__ void mma16816_acc(float* d, const uint32_t* a, const uint32_t* b) {
    asm volatile("mma.sync.aligned.m16n8k16.row.col.f32.f16.f16.f32 "
        "{%0,%1,%2,%3},{%4,%5,%6,%7},{%8,%9},{%0,%1,%2,%3};"
        : "+f"(d[0]), "+f"(d[1]), "+f"(d[2]), "+f"(d[3])
        : "r"(a[0]), "r"(a[1]), "r"(a[2]), "r"(a[3]), "r"(b[0]), "r"(b[1]));
}
// D = A*B + D  (m16n8k8)
__device__ __forceinline__ void mma1688_acc(float* d, const uint32_t* a, uint32_t b) {
    asm volatile("mma.sync.aligned.m16n8k8.row.col.f32.f16.f16.f32 "
        "{%0,%1,%2,%3},{%4,%5},{%6},{%0,%1,%2,%3};"
        : "+f"(d[0]), "+f"(d[1]), "+f"(d[2]), "+f"(d[3])
        : "r"(a[0]), "r"(a[1]), "r"(b));
}

// ---------------------------------------------------------------------------
// zero + counting sort (indices only) + gather
// ---------------------------------------------------------------------------
__global__ void k_zero_agg() {
    int i = blockIdx.x * 256 + threadIdx.x;
    ((float4*)g_agg)[i] = make_float4(0.f, 0.f, 0.f, 0.f);
}
__global__ void k_zero_cnt() {
    int i = blockIdx.x * 256 + threadIdx.x;
    ((int4*)g_cnt)[i] = make_int4(0, 0, 0, 0);
}
__global__ void k_hist(const int* __restrict__ labels) {
    int i = blockIdx.x * 256 + threadIdx.x;
    if (i < N_PTS) atomicAdd(&g_cnt[labels[i]], 1);
}
__global__ __launch_bounds__(256) void k_scan1() {
    __shared__ int sp[256];
    int t = threadIdx.x, b = blockIdx.x;
    int base = b * 1024 + t * 4;
    int4 c = *(const int4*)(g_cnt + base);
    int sum = c.x + c.y + c.z + c.w;
    sp[t] = sum;
    __syncthreads();
    for (int o = 1; o < 256; o <<= 1) {
        int v = (t >= o) ? sp[t - o] : 0;
        __syncthreads();
        sp[t] += v;
        __syncthreads();
    }
    int excl = sp[t] - sum;
    int4 ov;
    ov.x = excl; ov.y = excl + c.x; ov.z = ov.y + c.y; ov.w = ov.z + c.z;
    *(int4*)(g_cur + base) = ov;
    if (t == 255) g_bsum[b] = sp[255];
}
__global__ void k_scan2() {
    __shared__ int sp[64];
    int t = threadIdx.x;
    int v = g_bsum[t];
    sp[t] = v;
    __syncthreads();
    for (int o = 1; o < 64; o <<= 1) {
        int u = (t >= o) ? sp[t - o] : 0;
        __syncthreads();
        sp[t] += u;
        __syncthreads();
    }
    g_bsum[t] = sp[t] - v;
}
__global__ __launch_bounds__(256) void k_scan3() {
    int t = threadIdx.x, b = blockIdx.x;
    int off = g_bsum[b];
    int base = b * 1024 + t * 4;
    int4 v = *(const int4*)(g_cur + base);
    v.x += off; v.y += off; v.z += off; v.w += off;
    *(int4*)(g_cur + base) = v;
}
__global__ void k_scatter(const int* __restrict__ labels) {
    int i = blockIdx.x * 256 + threadIdx.x;
    if (i >= N_PTS) return;
    int l = labels[i];
    int pos = atomicAdd(&g_cur[l], 1);
    g_perm[pos] = i;
    g_slbl[pos] = l;
}
__global__ void k_gather(const float* __restrict__ pf,
                         const float* __restrict__ pts,
                         const float* __restrict__ cc) {
    int pos = blockIdx.x * 256 + threadIdx.x;
    if (pos >= N_PTS) return;
    int i = g_perm[pos];
    int l = g_slbl[pos];
    g_p0[pos] = ((const float4*)pf)[(size_t)i * 2];
    g_p1[pos] = ((const float4*)pf)[(size_t)i * 2 + 1];
    float d0 = cc[(size_t)l * 3 + 0] - pts[(size_t)i * 3 + 0];
    float d1 = cc[(size_t)l * 3 + 1] - pts[(size_t)i * 3 + 1];
    float d2 = cc[(size_t)l * 3 + 2] - pts[(size_t)i * 3 + 2];
    g_p2[pos] = make_float4(d0, d1, d2, 0.0f);
}

// ---------------------------------------------------------------------------
// k_point: tensor-core MLP. Each warp: GRP groups of 16 sorted points.
// All layers via mma.sync f16xf16->f32. Epilogue: smem transpose +
// label-run-merged red.v2 scatter.
// ---------------------------------------------------------------------------
__global__ __launch_bounds__(256, 2) void k_point(
    const float* __restrict__ we0, const float* __restrict__ be0,
    const float* __restrict__ we1, const float* __restrict__ be1,
    const float* __restrict__ we2, const float* __restrict__ be2,
    const float* __restrict__ we3, const float* __restrict__ be3,
    const float* __restrict__ wa0, const float* __restrict__ ba0,
    const float* __restrict__ wa1, const float* __restrict__ ba1)
{
    __shared__ float stp[WPB][16 * 72];   // staging + transpose (reused)
    __shared__ int   slb[WPB][16];

    const int lane = threadIdx.x & 31;
    const int wid  = threadIdx.x >> 5;
    const int g    = lane >> 2;        // 0..7  (row group / n index)
    const int k0   = (lane & 3) * 2;   // 0,2,4,6

    float* W = stp[wid];

    // ---- per-lane B fragments (weights constant; built once) ----
    // attention wa0 [11,64] (pad k to 16 with zeros)
    uint32_t bA[8][2];
#pragma unroll
    for (int t = 0; t < 8; t++) {
        int n = t * 8 + g;
        bA[t][0] = h2u(wa0[k0 * 64 + n], wa0[(k0 + 1) * 64 + n]);            // k0,k0+1 < 8 < 11
        bA[t][1] = h2u(k0 + 8 < 11 ? wa0[(k0 + 8) * 64 + n] : 0.f,
                       k0 + 9 < 11 ? wa0[(k0 + 9) * 64 + n] : 0.f);
    }
    // we0 [11,8]
    uint32_t bE0[2];
    {
        int n = g;
        bE0[0] = h2u(we0[k0 * 8 + n], we0[(k0 + 1) * 8 + n]);
        bE0[1] = h2u(k0 + 8 < 11 ? we0[(k0 + 8) * 8 + n] : 0.f,
                     k0 + 9 < 11 ? we0[(k0 + 9) * 8 + n] : 0.f);
    }
    // we1 [8,16] (k8)
    uint32_t bE1[2];
#pragma unroll
    for (int t = 0; t < 2; t++) {
        int n = t * 8 + g;
        bE1[t] = h2u(we1[k0 * 16 + n], we1[(k0 + 1) * 16 + n]);
    }
    // we2 [16,32] (k16)
    uint32_t bE2[4][2];
#pragma unroll
    for (int t = 0; t < 4; t++) {
        int n = t * 8 + g;
        bE2[t][0] = h2u(we2[k0 * 32 + n], we2[(k0 + 1) * 32 + n]);
        bE2[t][1] = h2u(we2[(k0 + 8) * 32 + n], we2[(k0 + 9) * 32 + n]);
    }
    // we3 [32,64] (two k16 blocks)
    uint32_t bL3a[8][2], bL3b[8][2];
#pragma unroll
    for (int t = 0; t < 8; t++) {
        int n = t * 8 + g;
        bL3a[t][0] = h2u(we3[k0 * 64 + n],        we3[(k0 + 1) * 64 + n]);
        bL3a[t][1] = h2u(we3[(k0 + 8) * 64 + n],  we3[(k0 + 9) * 64 + n]);
        bL3b[t][0] = h2u(we3[(k0 + 16) * 64 + n], we3[(k0 + 17) * 64 + n]);
        bL3b[t][1] = h2u(we3[(k0 + 24) * 64 + n], we3[(k0 + 25) * 64 + n]);
    }
    const float ba1s = ba1[0];

    const int grp0 = (blockIdx.x * WPB + wid) * GRP;

#pragma unroll 1
    for (int it = 0; it < GRP; it++) {
        const int grp = grp0 + it;
        if (grp >= N_GRPS) break;
        const int pos0 = grp * 16;

        __syncwarp();
        // stage 16 points: x[l] = [pf0..7, d0..2, 0,0,0,0,0] at W + l*72
        if (lane < 16) {
            float4 p0 = g_p0[pos0 + lane];
            float4 p1 = g_p1[pos0 + lane];
            float4 p2 = g_p2[pos0 + lane];
            float* xr = W + lane * 72;
            *(float4*)(xr + 0)  = p0;
            *(float4*)(xr + 4)  = p1;
            *(float4*)(xr + 8)  = make_float4(p2.x, p2.y, p2.z, 0.f);
            *(float4*)(xr + 12) = make_float4(0.f, 0.f, 0.f, 0.f);
            slb[wid][lane] = g_slbl[pos0 + lane];
        }
        __syncwarp();

        // A fragment of x [16 x 16]
        uint32_t ax[4];
        {
            const float* r1 = W + g * 72;
            const float* r2 = W + (g + 8) * 72;
            ax[0] = h2u(r1[k0],     r1[k0 + 1]);
            ax[1] = h2u(r2[k0],     r2[k0 + 1]);
            ax[2] = h2u(r1[k0 + 8], r1[k0 + 9]);
            ax[3] = h2u(r2[k0 + 8], r2[k0 + 9]);
        }

        // ----- attention: relu(x@wa0+ba0) @ wa1 + ba1 -> sigmoid -----
        float accA = 0.f, accB = 0.f;
#pragma unroll
        for (int t = 0; t < 8; t++) {
            float b0 = ba0[t * 8 + k0], b1v = ba0[t * 8 + k0 + 1];
            float d[4] = {b0, b1v, b0, b1v};
            mma16816_acc(d, ax, bA[t]);
            float w0 = wa1[t * 8 + k0], w1 = wa1[t * 8 + k0 + 1];
            accA += fmaxf(d[0], 0.f) * w0 + fmaxf(d[1], 0.f) * w1;
            accB += fmaxf(d[2], 0.f) * w0 + fmaxf(d[3], 0.f) * w1;
        }
        accA += __shfl_xor_sync(0xffffffffu, accA, 1);
        accA += __shfl_xor_sync(0xffffffffu, accA, 2);
        accB += __shfl_xor_sync(0xffffffffu, accB, 1);
        accB += __shfl_xor_sync(0xffffffffu, accB, 2);
        const float aA = 1.f / (1.f + __expf(-(accA + ba1s)));
        const float aB = 1.f / (1.f + __expf(-(accB + ba1s)));

        // ----- L0: 11->8 -----
        uint32_t h0f[2];
        {
            float b0 = be0[k0], b1v = be0[k0 + 1];
            float d[4] = {b0, b1v, b0, b1v};
            mma16816_acc(d, ax, bE0);
            h0f[0] = h2u(fmaxf(d[0], 0.f), fmaxf(d[1], 0.f));
            h0f[1] = h2u(fmaxf(d[2], 0.f), fmaxf(d[3], 0.f));
        }
        // ----- L1: 8->16 (k8, 2 tiles) -----
        uint32_t h1f[4];
#pragma unroll
        for (int t = 0; t < 2; t++) {
            float b0 = be1[t * 8 + k0], b1v = be1[t * 8 + k0 + 1];
            float d[4] = {b0, b1v, b0, b1v};
            mma1688_acc(d, h0f, bE1[t]);
            h1f[t * 2 + 0] = h2u(fmaxf(d[0], 0.f), fmaxf(d[1], 0.f));
            h1f[t * 2 + 1] = h2u(fmaxf(d[2], 0.f), fmaxf(d[3], 0.f));
        }
        // ----- L2: 16->32 (k16, 4 tiles) -----
        uint32_t h2a[4], h2b[4];
#pragma unroll
        for (int t = 0; t < 4; t++) {
            float b0 = be2[t * 8 + k0], b1v = be2[t * 8 + k0 + 1];
            float d[4] = {b0, b1v, b0, b1v};
            mma16816_acc(d, h1f, bE2[t]);
            uint32_t lo = h2u(fmaxf(d[0], 0.f), fmaxf(d[1], 0.f));
            uint32_t hi = h2u(fmaxf(d[2], 0.f), fmaxf(d[3], 0.f));
            if (t == 0)      { h2a[0] = lo; h2a[1] = hi; }
            else if (t == 1) { h2a[2] = lo; h2a[3] = hi; }
            else if (t == 2) { h2b[0] = lo; h2b[1] = hi; }
            else             { h2b[2] = lo; h2b[3] = hi; }
        }

        __syncwarp();   // x staging dead; safe to overwrite W below

        // ----- L3: 32->64, scale by attention, transpose-store -----
#pragma unroll
        for (int t = 0; t < 8; t++) {
            float b0 = be3[t * 8 + k0], b1v = be3[t * 8 + k0 + 1];
            float d[4] = {b0, b1v, b0, b1v};
            mma16816_acc(d, h2a, bL3a[t]);
            mma16816_acc(d, h2b, bL3b[t]);
            float v0 = fmaxf(d[0], 0.f) * aA;
            float v1 = fmaxf(d[1], 0.f) * aA;
            float v2 = fmaxf(d[2], 0.f) * aB;
            float v3 = fmaxf(d[3], 0.f) * aB;
            *(float2*)(W + g * 72 + t * 8 + k0)       = make_float2(v0, v1);
            *(float2*)(W + (g + 8) * 72 + t * 8 + k0) = make_float2(v2, v3);
        }
        __syncwarp();

        // ----- merge sorted label runs, scatter via red.v2 -----
        {
            const int c0 = 2 * lane;
            int cur = slb[wid][0];
            float2 s = *(const float2*)(W + c0);
#pragma unroll 1
            for (int p = 1; p < 16; p++) {
                int lb = slb[wid][p];
                float2 v = *(const float2*)(W + p * 72 + c0);
                if (lb == cur) { s.x += v.x; s.y += v.y; }
                else {
                    red2(g_agg + (size_t)cur * 64 + c0, s.x, s.y);
                    cur = lb; s = v;
                }
            }
            red2(g_agg + (size_t)cur * 64 + c0, s.x, s.y);
        }
    }
}

// ---------------------------------------------------------------------------
// Kernel 2: g_mid = relu(g_agg @ wo0 + bo0). 16 clusters/block.
// ---------------------------------------------------------------------------
__global__ __launch_bounds__(256) void k_mid(
    const float* __restrict__ wo0, const float* __restrict__ bo0)
{
    __shared__ float sw[64 * 128];
    __shared__ float sb[128];
    __shared__ __align__(16) float saggT[64 * 16];

    const int t  = threadIdx.x;
    const int cb = blockIdx.x * 16;

    for (int i = t; i < 8192; i += 256) sw[i] = wo0[i];
    if (t < 128) sb[t] = bo0[t];
    {
        int c  = t >> 4;
        int k4 = t & 15;
        float4 v = ((const float4*)g_agg)[(size_t)(cb + c) * 16 + k4];
        saggT[(k4 * 4 + 0) * 16 + c] = v.x;
        saggT[(k4 * 4 + 1) * 16 + c] = v.y;
        saggT[(k4 * 4 + 2) * 16 + c] = v.z;
        saggT[(k4 * 4 + 3) * 16 + c] = v.w;
    }
    __syncthreads();

    const int j    = t & 127;
    const int half = t >> 7;

    uint64_t acc[4];
    {
        float b = sb[j];
#pragma unroll
        for (int p = 0; p < 4; p++) acc[p] = pack2(b, b);
    }

#pragma unroll 4
    for (int k = 0; k < 64; k++) {
        float w = sw[k * 128 + j];
        uint64_t w2 = pack2(w, w);
        const uint64_t* row = (const uint64_t*)(saggT + k * 16) + half * 4;
        ulonglong2 m0 = *(const ulonglong2*)(row);
        ulonglong2 m1 = *(const ulonglong2*)(row + 2);
        acc[0] = fma2(m0.x, w2, acc[0]);
        acc[1] = fma2(m0.y, w2, acc[1]);
        acc[2] = fma2(m1.x, w2, acc[2]);
        acc[3] = fma2(m1.y, w2, acc[3]);
    }

    const int group = blockIdx.x >> 1;
    const int lane0 = (blockIdx.x & 1) * 16 + half * 8;
    float* dst = g_mid + (size_t)group * 4096 + (size_t)j * 32 + lane0;
#pragma unroll
    for (int p = 0; p < 4; p++) {
        float2 f = unpack2(acc[p]);
        f.x = fmaxf(f.x, 0.0f); f.y = fmaxf(f.y, 0.0f);
        ((float2*)dst)[p] = f;
    }
}

// ---------------------------------------------------------------------------
// Kernel 3: out = relu(g_mid @ wo1 + bo1). 32 clusters/block, 128 threads.
// ---------------------------------------------------------------------------
__global__ __launch_bounds__(128) void k_out(
    const float* __restrict__ wo1, const float* __restrict__ bo1,
    float* __restrict__ out)
{
    __shared__ __align__(16) uint64_t smid[128 * 16];

    const int t    = threadIdx.x;
    const int cg   = t & 63;
    const int half = t >> 6;
    const int grp  = blockIdx.x;

    const uint64_t* gm = (const uint64_t*)(g_mid + (size_t)grp * 4096);
    for (int i = t; i < 2048; i += 128) smid[i] = gm[i];
    __syncthreads();

    uint64_t acc[4][8];
    {
        float4 b = ((const float4*)bo1)[cg];
#pragma unroll
        for (int p = 0; p < 8; p++) {
            acc[0][p] = pack2(b.x, b.x); acc[1][p] = pack2(b.y, b.y);
            acc[2][p] = pack2(b.z, b.z); acc[3][p] = pack2(b.w, b.w);
        }
    }

    const float4* w4p = (const float4*)wo1;
#pragma unroll 4
    for (int k = 0; k < 128; k++) {
        float4 w = w4p[k * 64 + cg];
        uint64_t wd0 = pack2(w.x, w.x), wd1 = pack2(w.y, w.y);
        uint64_t wd2 = pack2(w.z, w.z), wd3 = pack2(w.w, w.w);
        const uint64_t* mrow = smid + k * 16 + half * 8;
        ulonglong2 m0 = *(const ulonglong2*)(mrow);
        ulonglong2 m1 = *(const ulonglong2*)(mrow + 2);
        ulonglong2 m2 = *(const ulonglong2*)(mrow + 4);
        ulonglong2 m3 = *(const ulonglong2*)(mrow + 6);
        uint64_t m[8] = {m0.x, m0.y, m1.x, m1.y, m2.x, m2.y, m3.x, m3.y};
#pragma unroll
        for (int p = 0; p < 8; p++) {
            acc[0][p] = fma2(m[p], wd0, acc[0][p]);
            acc[1][p] = fma2(m[p], wd1, acc[1][p]);
            acc[2][p] = fma2(m[p], wd2, acc[2][p]);
            acc[3][p] = fma2(m[p], wd3, acc[3][p]);
        }
    }

#pragma unroll
    for (int p = 0; p < 8; p++) {
        int pp = half * 8 + p;
        int c0 = grp * 32 + 2 * pp;
        float2 f0 = unpack2(acc[0][p]), f1 = unpack2(acc[1][p]);
        float2 f2 = unpack2(acc[2][p]), f3 = unpack2(acc[3][p]);
        float4 o0 = make_float4(fmaxf(f0.x, 0.f), fmaxf(f1.x, 0.f),
                                fmaxf(f2.x, 0.f), fmaxf(f3.x, 0.f));
        float4 o1 = make_float4(fmaxf(f0.y, 0.f), fmaxf(f1.y, 0.f),
                                fmaxf(f2.y, 0.f), fmaxf(f3.y, 0.f));
        *(float4*)(out + (size_t)c0 * 256 + 4 * cg)       = o0;
        *(float4*)(out + (size_t)(c0 + 1) * 256 + 4 * cg) = o1;
    }
}

// ---------------------------------------------------------------------------
extern "C" void kernel_launch(void* const* d_in, const int* in_sizes, int n_in,
                              void* d_out, int out_size)
{
    const float* pf     = (const float*)d_in[0];
    const int*   labels = (const int*)  d_in[1];
    const float* cc     = (const float*)d_in[2];
    const float* pts    = (const float*)d_in[3];
    const float* we0    = (const float*)d_in[4];
    const float* be0    = (const float*)d_in[5];
    const float* we1    = (const float*)d_in[6];
    const float* be1    = (const float*)d_in[7];
    const float* we2    = (const float*)d_in[8];
    const float* be2    = (const float*)d_in[9];
    const float* we3    = (const float*)d_in[10];
    const float* be3    = (const float*)d_in[11];
    const float* wa0    = (const float*)d_in[12];
    const float* ba0    = (const float*)d_in[13];
    const float* wa1    = (const float*)d_in[14];
    const float* ba1    = (const float*)d_in[15];
    const float* wo0    = (const float*)d_in[16];
    const float* bo0    = (const float*)d_in[17];
    const float* wo1    = (const float*)d_in[18];
    const float* bo1    = (const float*)d_in[19];
    float* out = (float*)d_out;

    k_zero_agg<<<N_CLU * 64 / 4 / 256, 256>>>();
    k_zero_cnt<<<N_CLU / 4 / 256, 256>>>();
    k_hist<<<(N_PTS + 255) / 256, 256>>>(labels);
    k_scan1<<<64, 256>>>();
    k_scan2<<<1, 64>>>();
    k_scan3<<<64, 256>>>();
    k_scatter<<<(N_PTS + 255) / 256, 256>>>(labels);
    k_gather<<<(N_PTS + 255) / 256, 256>>>(pf, pts, cc);
    k_point<<<PT_BLOCKS, 256>>>(we0, be0, we1, be1, we2, be2, we3, be3,
                                wa0, ba0, wa1, ba1);
    k_mid<<<N_CLU / 16, 256>>>(wo0, bo0);
    k_out<<<N_CLU / 32, 128>>>(wo1, bo1, out);
}